// round 7
// baseline (speedup 1.0000x reference)
#include <cuda_runtime.h>
#include <cuda_bf16.h>
#include <cstdint>

// ---------------------------------------------------------------------------
// GCN VGAE encoder — gather fused into consumer GEMM.
//   dinv = rsqrt(indeg+1); CSR by dst built on the fly.
//   GEMM1: hs1 = (X @ W1) * dinv[row]
//   fused GEMM2: per-row x = relu(dinv*(hs1[row] + sum_in hs1[src]) + b1)
//                hs2 = (x @ W2) * dinv[row]
//   fused GEMM3: per-row x = relu(dinv*(hs2[row] + sum_in hs2[src]) + b2)
//                [mu|lv] = x @ [Wmu|Wlv] + bias
// Warp-local X staging: warp ty computes/consumes only rows ty*8..ty*8+7.
// Scratch = __device__ globals, referenced ONLY from device code.
// ---------------------------------------------------------------------------

#define MAXN 50000
#define MAXE 800000
#define FDIM 128

__device__ float g_dinv[MAXN];
__device__ int   g_degi[MAXN];
__device__ int   g_off [MAXN + 1];
__device__ int   g_cur [MAXN];
__device__ int   g_csr [MAXE];
__device__ int   g_bsum[256];
__device__ float g_hs1 [MAXN * FDIM];
__device__ float g_hs2 [MAXN * FDIM];

typedef unsigned long long ull;

#define SPLAT2(d, x) asm("mov.b64 %0, {%1, %1};" : "=l"(d) : "f"(x))
#define FMA2(d, a, b, c) \
    asm("fma.rn.f32x2 %0, %1, %2, %3;" : "=l"(d) : "l"(a), "l"(b), "l"(c))
#define UNPACK2(lo, hi, v) \
    asm("mov.b64 {%0, %1}, %2;" : "=f"(lo), "=f"(hi) : "l"(v))

// ======================= degree + CSR build =======================

__global__ void zero_deg_kernel(int N) {
    int i = blockIdx.x * blockDim.x + threadIdx.x;
    if (i < N) g_degi[i] = 0;
}

__global__ void count_deg_kernel(const int* __restrict__ ei, int E) {
    int e = blockIdx.x * blockDim.x + threadIdx.x;
    if (e < E) atomicAdd(&g_degi[ei[E + e]], 1);
}

// block sums of deg, 256 nodes per block
__global__ void scan1_kernel(int N) {
    __shared__ int s[256];
    int t = threadIdx.x;
    int i = blockIdx.x * 256 + t;
    s[t] = (i < N) ? g_degi[i] : 0;
    __syncthreads();
#pragma unroll
    for (int d = 128; d > 0; d >>= 1) {
        if (t < d) s[t] += s[t + d];
        __syncthreads();
    }
    if (t == 0) g_bsum[blockIdx.x] = s[0];
}

// per-block scan (with redundant block-sum scan) -> off, cur, dinv
__global__ void scan3_kernel(int N, int nb) {
    __shared__ int bs[256];
    __shared__ int s[256];
    int t = threadIdx.x;

    int bv = (t < nb) ? g_bsum[t] : 0;
    bs[t] = bv;
    __syncthreads();
#pragma unroll
    for (int d = 1; d < 256; d <<= 1) {
        int v = (t >= d) ? bs[t - d] : 0;
        __syncthreads();
        bs[t] += v;
        __syncthreads();
    }
    // exclusive prefix of bsum for this block:
    int base = bs[blockIdx.x] - ((blockIdx.x < nb) ? g_bsum[blockIdx.x] : 0);

    int i = blockIdx.x * 256 + t;
    int deg = (i < N) ? g_degi[i] : 0;
    s[t] = deg;
    __syncthreads();
#pragma unroll
    for (int d = 1; d < 256; d <<= 1) {
        int v = (t >= d) ? s[t - d] : 0;
        __syncthreads();
        s[t] += v;
        __syncthreads();
    }
    if (i < N) {
        int off = base + s[t] - deg;
        g_off[i] = off;
        g_cur[i] = off;
        g_dinv[i] = rsqrtf((float)deg + 1.0f);
        if (i == N - 1) g_off[N] = off + deg;
    }
}

__global__ void fill_csr_kernel(const int* __restrict__ ei, int E) {
    int e = blockIdx.x * blockDim.x + threadIdx.x;
    if (e < E) {
        int d = ei[E + e];
        int pos = atomicAdd(&g_cur[d], 1);
        g_csr[pos] = ei[e];
    }
}

// ======================= GEMM machinery =======================
// 256 threads, tile 64 rows x 128 cols. tx=t&31 -> cols tx*4..+3 ;
// ty=t>>5 (8 warps) -> rows ty*8..+7. Ws[128][128] + Xs[64][128] = 96KB smem.

#define GEMM_SMEM ((128 * 128 + 64 * 128) * 4)

// 64x128x128 tile product. 8 rows x 4 cols (2 f32x2) per thread.
__device__ __forceinline__ void mm_tile(const float* Ws, const float* Xs,
                                        int c0, int r0, ull acc[8][2]) {
#pragma unroll
    for (int i = 0; i < 8; i++) { acc[i][0] = 0ull; acc[i][1] = 0ull; }

#pragma unroll 2
    for (int k0 = 0; k0 < 128; k0 += 4) {
        float4 a[8];
#pragma unroll
        for (int i = 0; i < 8; i++)
            a[i] = *(const float4*)(Xs + (r0 + i) * 128 + k0);
#pragma unroll
        for (int kk = 0; kk < 4; kk++) {
            ulonglong2 w = *(const ulonglong2*)(Ws + (k0 + kk) * 128 + c0);
#pragma unroll
            for (int i = 0; i < 8; i++) {
                ull s;
                SPLAT2(s, ((const float*)&a[i])[kk]);
                FMA2(acc[i][0], s, w.x, acc[i][0]);
                FMA2(acc[i][1], s, w.y, acc[i][1]);
            }
        }
    }
}

// Warp-local gathered X staging: warp stages its 8 rows from hs + CSR.
// x_row = relu(dinv[row]*(hs[row] + sum_{src in CSR[row]} hs[src]) + bias)
__device__ __forceinline__ void gather_stage(float* Xs, const float* __restrict__ hs,
                                             const float* __restrict__ bias,
                                             int rowBase, int N, int t) {
    const int lane = t & 31, ty = t >> 5;
    const float4* hs4 = (const float4*)hs;
    float4 bb = ((const float4*)bias)[lane];
#pragma unroll
    for (int i = 0; i < 8; i++) {
        int r = ty * 8 + i;
        int rg = rowBase + r;
        float4 acc = make_float4(0.f, 0.f, 0.f, 0.f);
        if (rg < N) {
            acc = hs4[(size_t)rg * 32 + lane];   // self-loop
            int j = g_off[rg], end = g_off[rg + 1];
            for (; j + 4 <= end; j += 4) {
                int s0 = g_csr[j], s1 = g_csr[j + 1];
                int s2 = g_csr[j + 2], s3 = g_csr[j + 3];
                float4 v0 = hs4[(size_t)s0 * 32 + lane];
                float4 v1 = hs4[(size_t)s1 * 32 + lane];
                float4 v2 = hs4[(size_t)s2 * 32 + lane];
                float4 v3 = hs4[(size_t)s3 * 32 + lane];
                v0.x += v1.x; v0.y += v1.y; v0.z += v1.z; v0.w += v1.w;
                v2.x += v3.x; v2.y += v3.y; v2.z += v3.z; v2.w += v3.w;
                acc.x += v0.x + v2.x; acc.y += v0.y + v2.y;
                acc.z += v0.z + v2.z; acc.w += v0.w + v2.w;
            }
            for (; j < end; j++) {
                float4 v = hs4[(size_t)g_csr[j] * 32 + lane];
                acc.x += v.x; acc.y += v.y; acc.z += v.z; acc.w += v.w;
            }
            float dv = g_dinv[rg];
            acc.x = fmaxf(acc.x * dv + bb.x, 0.f);
            acc.y = fmaxf(acc.y * dv + bb.y, 0.f);
            acc.z = fmaxf(acc.z * dv + bb.z, 0.f);
            acc.w = fmaxf(acc.w * dv + bb.w, 0.f);
        }
        ((float4*)Xs)[r * 32 + lane] = acc;
    }
    __syncwarp();
}

// ---------------- GEMM1: hs1 = (X @ W1) * dinv ----------------

__global__ void __launch_bounds__(256)
gemm1_kernel(const float* __restrict__ xin, const float* __restrict__ W, int N) {
    extern __shared__ float sm[];
    float* Ws = sm;
    float* Xs = sm + 128 * 128;
    const int t = threadIdx.x;

#pragma unroll
    for (int i = 0; i < 16; i++) {
        int idx = t + i * 256;
        ((float4*)Ws)[idx] = ((const float4*)W)[idx];
    }
    const int rowBase = blockIdx.x * 64;
#pragma unroll
    for (int i = 0; i < 8; i++) {
        int idx = t + i * 256;
        int r = idx >> 5, c4 = idx & 31;
        int rg = rowBase + r;
        float4 v = make_float4(0.f, 0.f, 0.f, 0.f);
        if (rg < N) v = ((const float4*)xin)[(size_t)rg * 32 + c4];
        ((float4*)Xs)[idx] = v;
    }
    __syncthreads();

    const int tx = t & 31, ty = t >> 5;
    const int c0 = tx * 4, r0 = ty * 8;
    ull acc[8][2];
    mm_tile(Ws, Xs, c0, r0, acc);

#pragma unroll
    for (int i = 0; i < 8; i++) {
        int r = rowBase + r0 + i;
        if (r < N) {
            float dv = g_dinv[r];
            float a0, a1, a2, a3;
            UNPACK2(a0, a1, acc[i][0]);
            UNPACK2(a2, a3, acc[i][1]);
            *(float4*)(g_hs1 + (size_t)r * 128 + c0) =
                make_float4(a0 * dv, a1 * dv, a2 * dv, a3 * dv);
        }
    }
}

// ------- fused GEMM2: x = relu(dinv*gather(hs1)+b1); hs2 = (x@W2)*dinv -------

__global__ void __launch_bounds__(256)
gemm2_fused_kernel(const float* __restrict__ W,
                   const float* __restrict__ bias, int N) {
    extern __shared__ float sm[];
    float* Ws = sm;
    float* Xs = sm + 128 * 128;
    const int t = threadIdx.x;

#pragma unroll
    for (int i = 0; i < 16; i++) {
        int idx = t + i * 256;
        ((float4*)Ws)[idx] = ((const float4*)W)[idx];
    }
    __syncthreads();   // Ws ready; Xs staging is warp-local

    const int rowBase = blockIdx.x * 64;
    gather_stage(Xs, (const float*)g_hs1, bias, rowBase, N, t);

    const int tx = t & 31, ty = t >> 5;
    const int c0 = tx * 4, r0 = ty * 8;
    ull acc[8][2];
    mm_tile(Ws, Xs, c0, r0, acc);

#pragma unroll
    for (int i = 0; i < 8; i++) {
        int r = rowBase + r0 + i;
        if (r < N) {
            float dv = g_dinv[r];
            float a0, a1, a2, a3;
            UNPACK2(a0, a1, acc[i][0]);
            UNPACK2(a2, a3, acc[i][1]);
            *(float4*)(g_hs2 + (size_t)r * 128 + c0) =
                make_float4(a0 * dv, a1 * dv, a2 * dv, a3 * dv);
        }
    }
}

// -- fused GEMM3: x = relu(dinv*gather(hs2)+b2); [mu|lv] = x@[Wmu|Wlv]+bias --

__global__ void __launch_bounds__(256)
gemm3_fused_kernel(const float* __restrict__ Wmu,
                   const float* __restrict__ Wlv,
                   const float* __restrict__ bmu,
                   const float* __restrict__ blv,
                   const float* __restrict__ b2,
                   float* __restrict__ out, int N) {
    extern __shared__ float sm[];
    float* Ws = sm;
    float* Xs = sm + 128 * 128;
    const int t = threadIdx.x;

#pragma unroll
    for (int i = 0; i < 16; i++) {
        int idx = t + i * 256;
        int k = idx >> 5;
        int cc4 = idx & 31;
        float4 v = (cc4 < 16) ? ((const float4*)Wmu)[k * 16 + cc4]
                              : ((const float4*)Wlv)[k * 16 + (cc4 - 16)];
        ((float4*)Ws)[idx] = v;
    }
    __syncthreads();

    const int rowBase = blockIdx.x * 64;
    gather_stage(Xs, (const float*)g_hs2, b2, rowBase, N, t);

    const int tx = t & 31, ty = t >> 5;
    const int c0 = tx * 4, r0 = ty * 8;
    ull acc[8][2];
    mm_tile(Ws, Xs, c0, r0, acc);

    const bool is_mu = (c0 < 64);
    const int cl = is_mu ? c0 : (c0 - 64);
    float4 bs = is_mu ? *(const float4*)(bmu + cl) : *(const float4*)(blv + cl);
#pragma unroll
    for (int i = 0; i < 8; i++) {
        int r = rowBase + r0 + i;
        if (r < N) {
            float a0, a1, a2, a3;
            UNPACK2(a0, a1, acc[i][0]);
            UNPACK2(a2, a3, acc[i][1]);
            float* base = is_mu ? (out + (size_t)r * 64 + cl)
                                : (out + (size_t)N * 64 + (size_t)r * 64 + cl);
            *(float4*)base = make_float4(a0 + bs.x, a1 + bs.y, a2 + bs.z, a3 + bs.w);
        }
    }
}

// ======================= launch =======================

extern "C" void kernel_launch(void* const* d_in, const int* in_sizes, int n_in,
                              void* d_out, int out_size) {
    const float* x   = (const float*)d_in[0];
    const int*   ei  = (const int*)d_in[1];      // int32 edge_index [2, E]
    const float* W1  = (const float*)d_in[2];
    const float* b1  = (const float*)d_in[3];
    const float* W2  = (const float*)d_in[4];
    const float* b2  = (const float*)d_in[5];
    const float* Wmu = (const float*)d_in[6];
    const float* bmu = (const float*)d_in[7];
    const float* Wlv = (const float*)d_in[8];
    const float* blv = (const float*)d_in[9];
    float* out = (float*)d_out;

    const int N = in_sizes[0] / 128;
    const int E = in_sizes[1] / 2;

    cudaFuncSetAttribute(gemm1_kernel,
                         cudaFuncAttributeMaxDynamicSharedMemorySize, GEMM_SMEM);
    cudaFuncSetAttribute(gemm2_fused_kernel,
                         cudaFuncAttributeMaxDynamicSharedMemorySize, GEMM_SMEM);
    cudaFuncSetAttribute(gemm3_fused_kernel,
                         cudaFuncAttributeMaxDynamicSharedMemorySize, GEMM_SMEM);

    const int nb = (N + 255) / 256;               // <= 256 for N <= 65536
    const int gemm_blocks = (N + 63) / 64;

    // degree + CSR
    zero_deg_kernel<<<nb, 256>>>(N);
    count_deg_kernel<<<(E + 255) / 256, 256>>>(ei, E);
    scan1_kernel<<<nb, 256>>>(N);
    scan3_kernel<<<nb, 256>>>(N, nb);
    fill_csr_kernel<<<(E + 255) / 256, 256>>>(ei, E);

    // pipeline
    gemm1_kernel<<<gemm_blocks, 256, GEMM_SMEM>>>(x, W1, N);
    gemm2_fused_kernel<<<gemm_blocks, 256, GEMM_SMEM>>>(W2, b1, N);
    gemm3_fused_kernel<<<gemm_blocks, 256, GEMM_SMEM>>>(Wmu, Wlv, bmu, blv, b2, out, N);
}